// round 15
// baseline (speedup 1.0000x reference)
#include <cuda_runtime.h>
#include <cuda_fp16.h>
#include <math.h>
#include <stdint.h>

#define SEQ 2048
#define HID 2048
#define NHEAD 32
#define HDIM 64
#define ISZ 8192
#define NLAYER 2

// ======================= scratch (static device arrays) =======================
__device__ float g_x  [SEQ * HID];
__device__ __half g_q  [SEQ * HID];
__device__ __half g_k  [SEQ * HID];
__device__ __half g_v  [SEQ * HID];
__device__ __half g_h  [SEQ * HID];
__device__ __half g_ctx[SEQ * HID];
__device__ __half g_mid[SEQ * ISZ];
// fp16 weights, SAME layout as inputs: W[K][N]
__device__ __half g_wqh[NLAYER * HID * HID];
__device__ __half g_wkh[NLAYER * HID * HID];
__device__ __half g_wvh[NLAYER * HID * HID];
__device__ __half g_woh[NLAYER * HID * HID];
__device__ __half g_w1h[NLAYER * HID * ISZ];
__device__ __half g_w2h[NLAYER * ISZ * HID];

// ======================= PTX helpers =======================
__device__ __forceinline__ uint32_t smem_u32(const void* p) {
    uint32_t a;
    asm("{ .reg .u64 t; cvta.to.shared.u64 t, %1; cvt.u32.u64 %0, t; }" : "=r"(a) : "l"(p));
    return a;
}
__device__ __forceinline__ void cp16(uint32_t dst, const void* src) {
    asm volatile("cp.async.cg.shared.global [%0], [%1], 16;" :: "r"(dst), "l"(src));
}
__device__ __forceinline__ void cp_commit() {
    asm volatile("cp.async.commit_group;" ::: "memory");
}
template <int N>
__device__ __forceinline__ void cp_wait() {
    asm volatile("cp.async.wait_group %0;" :: "n"(N) : "memory");
}
__device__ __forceinline__ void ldmx4(uint32_t* r, uint32_t addr) {
    asm volatile("ldmatrix.sync.aligned.m8n8.x4.shared.b16 {%0,%1,%2,%3}, [%4];"
                 : "=r"(r[0]), "=r"(r[1]), "=r"(r[2]), "=r"(r[3]) : "r"(addr));
}
__device__ __forceinline__ void ldmx4t(uint32_t* r, uint32_t addr) {
    asm volatile("ldmatrix.sync.aligned.m8n8.x4.trans.shared.b16 {%0,%1,%2,%3}, [%4];"
                 : "=r"(r[0]), "=r"(r[1]), "=r"(r[2]), "=r"(r[3]) : "r"(addr));
}
__device__ __forceinline__ void mma16816h(float* d, const uint32_t* a, const uint32_t* b) {
    asm volatile("mma.sync.aligned.m16n8k16.row.col.f32.f16.f16.f32 "
                 "{%0,%1,%2,%3}, {%4,%5,%6,%7}, {%8,%9}, {%0,%1,%2,%3};"
                 : "+f"(d[0]), "+f"(d[1]), "+f"(d[2]), "+f"(d[3])
                 : "r"(a[0]), "r"(a[1]), "r"(a[2]), "r"(a[3]), "r"(b[0]), "r"(b[1]));
}
__device__ __forceinline__ uint32_t packh2(float lo, float hi) {
    __half2 t = __floats2half2_rn(lo, hi);
    return *(uint32_t*)&t;
}

// ======================= small kernels =======================
__device__ __forceinline__ float gelu_tanh(float v) {
    float t = 0.7978845608028654f * v * (1.0f + 0.044715f * v * v);
    return 0.5f * v * (1.0f + tanhf(t));
}

// layernorm: single global read (values in registers), vectorized I/O
template <int HALF>
__global__ void __launch_bounds__(256) ln_kernel(const float* __restrict__ x,
                                                 const float* __restrict__ gamma,
                                                 float* __restrict__ outf,
                                                 __half* __restrict__ oh) {
    __shared__ float sh[18];
    int row = blockIdx.x;
    const float4* xr4 = (const float4*)(x + (long)row * HID);
    const float4* g4  = (const float4*)gamma;
    float4 v[2];
    float s = 0.f, s2 = 0.f;
    #pragma unroll
    for (int i = 0; i < 2; i++) {
        v[i] = xr4[threadIdx.x + i * 256];
        s  += v[i].x + v[i].y + v[i].z + v[i].w;
        s2 += v[i].x * v[i].x + v[i].y * v[i].y + v[i].z * v[i].z + v[i].w * v[i].w;
    }
    #pragma unroll
    for (int o = 16; o; o >>= 1) {
        s  += __shfl_xor_sync(0xFFFFFFFFu, s,  o);
        s2 += __shfl_xor_sync(0xFFFFFFFFu, s2, o);
    }
    int w = threadIdx.x >> 5, lane = threadIdx.x & 31;
    if (lane == 0) { sh[w] = s; sh[8 + w] = s2; }
    __syncthreads();
    if (threadIdx.x < 32) {
        s  = (threadIdx.x < 8) ? sh[threadIdx.x]     : 0.f;
        s2 = (threadIdx.x < 8) ? sh[8 + threadIdx.x] : 0.f;
        #pragma unroll
        for (int o = 4; o; o >>= 1) {
            s  += __shfl_xor_sync(0xFFFFFFFFu, s,  o);
            s2 += __shfl_xor_sync(0xFFFFFFFFu, s2, o);
        }
        if (threadIdx.x == 0) {
            float mu = s * (1.0f / HID);
            float var = s2 * (1.0f / HID) - mu * mu;
            sh[16] = mu;
            sh[17] = rsqrtf(var + 1e-5f);
        }
    }
    __syncthreads();
    float mu = sh[16], inv = sh[17];
    #pragma unroll
    for (int i = 0; i < 2; i++) {
        int i4 = threadIdx.x + i * 256;
        float4 g = g4[i4];
        float a = (v[i].x - mu) * inv * g.x;
        float b = (v[i].y - mu) * inv * g.y;
        float c = (v[i].z - mu) * inv * g.z;
        float d = (v[i].w - mu) * inv * g.w;
        if (HALF) {
            uint2 p;
            p.x = packh2(a, b);
            p.y = packh2(c, d);
            *(uint2*)(oh + (long)row * HID + i4 * 4) = p;
        } else {
            *(float4*)(outf + (long)row * HID + i4 * 4) = make_float4(a, b, c, d);
        }
    }
}

// ======================= batched weight convert (fp32 -> fp16, same layout) =======================
// One launch, 12 segments; each block converts 4096 elems (1024 float4).
#define NW 12
struct CDesc {
    const float* src[NW];
    __half* dst[NW];
    int off[NW + 1];   // block prefix offsets
};

__global__ void __launch_bounds__(256) wconv_all_kernel(CDesc d) {
    int bid = blockIdx.x;
    int m = 0;
    #pragma unroll
    for (int i = 0; i < NW; i++)
        if (bid >= d.off[i + 1]) m = i + 1;
    long base4 = (long)(bid - d.off[m]) * 1024;   // float4 units
    const float4* src = (const float4*)d.src[m];
    __half* dst = d.dst[m];
    #pragma unroll
    for (int j = 0; j < 4; j++) {
        long i4 = base4 + threadIdx.x + j * 256;
        float4 v = src[i4];
        uint2 p;
        p.x = packh2(v.x, v.y);
        p.y = packh2(v.z, v.w);
        *(uint2*)(dst + i4 * 4) = p;
    }
}

// ======================= persistent mma.sync fp16 GEMM (K-major B via ldmatrix.trans) =======================
// C[M,N] = A[M,K] @ W, W stored [K,N] row-major fp16 (same layout as input weights).
// BM=128, BN=128, BK=32; 4 warps, warp tile 64x64; 4-stage cp.async (64KB), 2 CTA/SM.
// A smem: [128 rows x 64B], chunk swizzle c ^ ((row>>1)&3).
// B smem: [32 rows(K) x 256B(N: 128 halves)], chunk swizzle c ^ (row & 15).
#define A_TILE 8192
#define B_TILE 8192
#define STAGE_BYTES (A_TILE + B_TILE)
#define NSTAGE 4
#define GSM_TOTAL (NSTAGE * STAGE_BYTES)
#define PERSIST_GRID 296

__device__ __forceinline__ void load_A_tile(uint32_t sbase, const __half* __restrict__ P,
                                            int K, long k0, int tid) {
    #pragma unroll
    for (int i = 0; i < 4; i++) {
        int idx = tid + i * 128;
        int row = idx >> 2, c = idx & 3;
        const __half* src = P + (long)row * K + k0 + c * 8;
        uint32_t dst = sbase + row * 64 + ((c ^ ((row >> 1) & 3)) << 4);
        cp16(dst, src);
    }
}
// B tile: rows = K (32), 256B per row covering 128 N columns starting at col0
__device__ __forceinline__ void load_B_tile(uint32_t sbase, const __half* __restrict__ W,
                                            int N, long k0, int col0, int tid) {
    #pragma unroll
    for (int i = 0; i < 4; i++) {
        int idx = tid + i * 128;
        int row = idx >> 4, c = idx & 15;
        const __half* src = W + (k0 + row) * (long)N + col0 + c * 8;
        uint32_t dst = sbase + row * 256 + ((c ^ (row & 15)) << 4);
        cp16(dst, src);
    }
}

template <int MODE>
__global__ void __launch_bounds__(128, 2) gemm_mma_kernel(
    const __half* __restrict__ A,
    const __half* __restrict__ B0, const __half* __restrict__ B1,
    const __half* __restrict__ B2,
    const float* __restrict__ bias, const float* res,
    float* Cf,
    __half* __restrict__ Ch0, __half* __restrict__ Ch1, __half* __restrict__ Ch2,
    int M, int N, int K, int ntx, int nty, int ntz)
{
    extern __shared__ char smem[];
    uint32_t sb = smem_u32(smem);
    int tid = threadIdx.x;
    int wid = tid >> 5, lane = tid & 31;
    int warp_m = wid >> 1, warp_n = wid & 1;
    int m0 = warp_m * 64;

    int grp = lane >> 3, lr = lane & 7;
    int rowA0 = m0 + (grp & 1) * 8 + lr;
    int ccA   = grp >> 1;
    int xA = (rowA0 >> 1) & 3;
    // B (trans) geometry: row = k, chunk = n/8   (attention PV pattern)
    int rowBk_off = (grp & 1) * 8 + lr;       // k within 16
    int ccB_off   = warp_n * 8 + (grp >> 1);  // n chunk base for this warp
    int nc = K / 32;
    int ntot = ntx * nty * ntz;

    for (int t = blockIdx.x; t < ntot; t += gridDim.x) {
        int z   = t / (ntx * nty);
        int rem = t - z * (ntx * nty);
        int by  = rem / ntx;
        int bx  = rem - by * ntx;
        int row0 = by * 128, col0 = bx * 128;

        const __half* B  = (z == 0) ? B0 : (z == 1) ? B1 : B2;
        __half* Ch = (z == 0) ? Ch0 : (z == 1) ? Ch1 : Ch2;

        const __half* pA = A + (long)row0 * K;

        float acc[4][8][4];
        #pragma unroll
        for (int i = 0; i < 4; i++)
            #pragma unroll
            for (int j = 0; j < 8; j++)
                #pragma unroll
                for (int q = 0; q < 4; q++) acc[i][j][q] = 0.f;

        __syncthreads();

        #pragma unroll
        for (int p = 0; p < 3; p++) {
            uint32_t st = sb + p * STAGE_BYTES;
            load_A_tile(st,          pA, K, (long)p * 32, tid);
            load_B_tile(st + A_TILE, B,  N, (long)p * 32, col0, tid);
            cp_commit();
        }

        int s_comp = 0, s_load = 3;
        for (int c = 0; c < nc; c++) {
            cp_wait<2>();
            __syncthreads();
            if (c + 3 < nc) {
                uint32_t st = sb + s_load * STAGE_BYTES;
                long k0 = (long)(c + 3) * 32;
                load_A_tile(st,          pA, K, k0, tid);
                load_B_tile(st + A_TILE, B,  N, k0, col0, tid);
            }
            cp_commit();

            uint32_t sA = sb + s_comp * STAGE_BYTES;
            uint32_t sB = sA + A_TILE;
            #pragma unroll
            for (int ks = 0; ks < 2; ks++) {
                uint32_t af[4][4], bf[4][4];
                #pragma unroll
                for (int mt = 0; mt < 4; mt++) {
                    uint32_t base = sA + (rowA0 + mt * 16) * 64;
                    ldmx4(af[mt], base + (((ks * 2 + ccA) ^ xA) << 4));
                }
                #pragma unroll
                for (int np = 0; np < 4; np++) {
                    int rk = ks * 16 + rowBk_off;
                    int cc = ccB_off + np * 2;
                    ldmx4t(bf[np], sB + rk * 256 + ((cc ^ (rk & 15)) << 4));
                }
                #pragma unroll
                for (int mt = 0; mt < 4; mt++)
                    #pragma unroll
                    for (int nt = 0; nt < 8; nt++)
                        mma16816h(acc[mt][nt], af[mt], &bf[nt >> 1][(nt & 1) * 2]);
            }
            s_comp = (s_comp + 1) & 3;
            s_load = (s_load + 1) & 3;
        }

        int n0 = warp_n * 64;
        int r = lane >> 2, c2 = (lane & 3) * 2;
        #pragma unroll
        for (int mt = 0; mt < 4; mt++) {
            #pragma unroll
            for (int nt = 0; nt < 8; nt++) {
                long gr = row0 + m0 + mt * 16 + r;
                long gc = col0 + n0 + nt * 8 + c2;
                #pragma unroll
                for (int hrow = 0; hrow < 2; hrow++) {
                    long grr = gr + hrow * 8;
                    float v0 = acc[mt][nt][hrow * 2 + 0];
                    float v1 = acc[mt][nt][hrow * 2 + 1];
                    if (MODE == 0) {
                        *(uint32_t*)(Ch + grr * N + gc) = packh2(v0, v1);
                    } else if (MODE == 1) {
                        float2 b = *(const float2*)(bias + gc);
                        float2 rr = *(const float2*)(res + grr * N + gc);
                        *(float2*)(Cf + grr * N + gc) = make_float2(v0 + b.x + rr.x, v1 + b.y + rr.y);
                    } else {
                        *(uint32_t*)(Ch + grr * N + gc) = packh2(gelu_tanh(v0), gelu_tanh(v1));
                    }
                }
            }
        }
    }
}

// ======================= tensor-core flash attention (plain fp16) =======================
#define AS_Q  0
#define AS_K0 16384
#define AS_V0 32768
#define AS_K1 49152
#define AS_V1 65536
#define AS_TOTAL 81920

__device__ __forceinline__ void stage_h(uint32_t sbase, const __half* __restrict__ src,
                                        int row0, int h, int tid) {
    #pragma unroll
    for (int i = 0; i < 4; i++) {
        int idx = tid + i * 256;
        int r = idx >> 3, c = idx & 7;
        cp16(sbase + r * 128 + ((c ^ (r & 7)) << 4),
             src + (long)(row0 + r) * HID + h * HDIM + c * 8);
    }
}

__global__ void __launch_bounds__(256) attn_mma_kernel(
    const __half* __restrict__ Q, const __half* __restrict__ K,
    const __half* __restrict__ V, __half* __restrict__ O)
{
    extern __shared__ char smem[];
    uint32_t sb = smem_u32(smem);
    int tid = threadIdx.x;
    int w = tid >> 5, lane = tid & 31;
    int qb = blockIdx.x, h = blockIdx.y;

    int grp = lane >> 3, lr = lane & 7;
    int rowQ = w * 16 + (grp & 1) * 8 + lr;
    int ccQ  = grp >> 1;
    int xQ = rowQ & 7;
    int rowK_off = (grp >> 1) * 8 + lr;
    int ccK  = grp & 1;
    int rowV_off = (grp & 1) * 8 + lr;
    int ccV_off  = grp >> 1;

    stage_h(sb + AS_Q,  Q, qb * 128, h, tid);
    stage_h(sb + AS_K0, K, 0,        h, tid);
    stage_h(sb + AS_V0, V, 0,        h, tid);
    cp_commit();
    cp_wait<0>();
    __syncthreads();

    uint32_t qf[4][4];
    #pragma unroll
    for (int ks = 0; ks < 4; ks++) {
        uint32_t base = sb + AS_Q + rowQ * 128;
        ldmx4(qf[ks], base + (((ks * 2 + ccQ) ^ xQ) << 4));
    }

    float oacc[8][4];
    #pragma unroll
    for (int i = 0; i < 8; i++)
        #pragma unroll
        for (int q = 0; q < 4; q++) oacc[i][q] = 0.f;
    float m0 = -1e30f, m1 = -1e30f, l0 = 0.f, l1 = 0.f;

    int qg0 = qb * 128 + w * 16 + (lane >> 2);
    int qg1 = qg0 + 8;
    const float scale = 0.125f;

    for (int kt = 0; kt <= qb; kt++) {
        uint32_t kb = sb + ((kt & 1) ? AS_K1 : AS_K0);
        uint32_t vb = sb + ((kt & 1) ? AS_V1 : AS_V0);
        if (kt < qb) {
            uint32_t kb2 = sb + ((kt & 1) ? AS_K0 : AS_K1);
            uint32_t vb2 = sb + ((kt & 1) ? AS_V0 : AS_V1);
            stage_h(kb2, K, (kt + 1) * 128, h, tid);
            stage_h(vb2, V, (kt + 1) * 128, h, tid);
            cp_commit();
        }

        float sacc[16][4];
        #pragma unroll
        for (int i = 0; i < 16; i++)
            #pragma unroll
            for (int q = 0; q < 4; q++) sacc[i][q] = 0.f;

        #pragma unroll
        for (int ks = 0; ks < 4; ks++) {
            #pragma unroll
            for (int nb = 0; nb < 8; nb++) {
                int rowK = nb * 16 + rowK_off;
                uint32_t bk[4];
                ldmx4(bk, kb + rowK * 128 + (((ks * 2 + ccK) ^ (rowK & 7)) << 4));
                mma16816h(sacc[nb * 2 + 0], qf[ks], &bk[0]);
                mma16816h(sacc[nb * 2 + 1], qf[ks], &bk[2]);
            }
        }
        #pragma unroll
        for (int nt = 0; nt < 16; nt++) {
            sacc[nt][0] *= scale; sacc[nt][1] *= scale;
            sacc[nt][2] *= scale; sacc[nt][3] *= scale;
        }

        if (kt == qb) {
            #pragma unroll
            for (int nt = 0; nt < 16; nt++) {
                int kg = kt * 128 + nt * 8 + 2 * (lane & 3);
                #pragma unroll
                for (int e = 0; e < 2; e++) {
                    if (kg + e > qg0) sacc[nt][e]     = -1e30f;
                    if (kg + e > qg1) sacc[nt][2 + e] = -1e30f;
                }
            }
        }

        float rm0 = -1e30f, rm1 = -1e30f;
        #pragma unroll
        for (int nt = 0; nt < 16; nt++) {
            rm0 = fmaxf(rm0, fmaxf(sacc[nt][0], sacc[nt][1]));
            rm1 = fmaxf(rm1, fmaxf(sacc[nt][2], sacc[nt][3]));
        }
        rm0 = fmaxf(rm0, __shfl_xor_sync(0xFFFFFFFFu, rm0, 1));
        rm0 = fmaxf(rm0, __shfl_xor_sync(0xFFFFFFFFu, rm0, 2));
        rm1 = fmaxf(rm1, __shfl_xor_sync(0xFFFFFFFFu, rm1, 1));
        rm1 = fmaxf(rm1, __shfl_xor_sync(0xFFFFFFFFu, rm1, 2));
        float mn0 = fmaxf(m0, rm0), mn1 = fmaxf(m1, rm1);
        float al0 = __expf(m0 - mn0), al1 = __expf(m1 - mn1);
        m0 = mn0; m1 = mn1;

        float rs0 = 0.f, rs1 = 0.f;
        #pragma unroll
        for (int nt = 0; nt < 16; nt++) {
            sacc[nt][0] = __expf(sacc[nt][0] - mn0);
            sacc[nt][1] = __expf(sacc[nt][1] - mn0);
            sacc[nt][2] = __expf(sacc[nt][2] - mn1);
            sacc[nt][3] = __expf(sacc[nt][3] - mn1);
            rs0 += sacc[nt][0] + sacc[nt][1];
            rs1 += sacc[nt][2] + sacc[nt][3];
        }
        rs0 += __shfl_xor_sync(0xFFFFFFFFu, rs0, 1);
        rs0 += __shfl_xor_sync(0xFFFFFFFFu, rs0, 2);
        rs1 += __shfl_xor_sync(0xFFFFFFFFu, rs1, 1);
        rs1 += __shfl_xor_sync(0xFFFFFFFFu, rs1, 2);
        l0 = l0 * al0 + rs0;
        l1 = l1 * al1 + rs1;

        #pragma unroll
        for (int i = 0; i < 8; i++) {
            oacc[i][0] *= al0; oacc[i][1] *= al0;
            oacc[i][2] *= al1; oacc[i][3] *= al1;
        }

        #pragma unroll
        for (int ks2 = 0; ks2 < 8; ks2++) {
            uint32_t ap[4];
            ap[0] = packh2(sacc[2 * ks2][0],     sacc[2 * ks2][1]);
            ap[1] = packh2(sacc[2 * ks2][2],     sacc[2 * ks2][3]);
            ap[2] = packh2(sacc[2 * ks2 + 1][0], sacc[2 * ks2 + 1][1]);
            ap[3] = packh2(sacc[2 * ks2 + 1][2], sacc[2 * ks2 + 1][3]);
            int rowV = ks2 * 16 + rowV_off;
            uint32_t vbase = vb + rowV * 128;
            #pragma unroll
            for (int db = 0; db < 4; db++) {
                int cc = db * 2 + ccV_off;
                uint32_t bv[4];
                ldmx4t(bv, vbase + ((cc ^ (rowV & 7)) << 4));
                mma16816h(oacc[db * 2 + 0], ap, &bv[0]);
                mma16816h(oacc[db * 2 + 1], ap, &bv[2]);
            }
        }

        if (kt < qb) {
            cp_wait<0>();
            __syncthreads();
        }
    }

    float i0 = 1.0f / l0, i1 = 1.0f / l1;
    long gr0 = qb * 128 + w * 16 + (lane >> 2);
    long gc0 = h * HDIM + 2 * (lane & 3);
    #pragma unroll
    for (int nto = 0; nto < 8; nto++) {
        long gc = gc0 + nto * 8;
        *(uint32_t*)(O + gr0 * HID + gc)       = packh2(oacc[nto][0] * i0, oacc[nto][1] * i0);
        *(uint32_t*)(O + (gr0 + 8) * HID + gc) = packh2(oacc[nto][2] * i1, oacc[nto][3] * i1);
    }
}

// ======================= orchestration =======================
extern "C" void kernel_launch(void* const* d_in, const int* in_sizes, int n_in,
                              void* d_out, int out_size) {
    const float* emb = (const float*)d_in[0];
    const float* Wq = (const float*)d_in[2];
    const float* Wk = (const float*)d_in[3];
    const float* Wv = (const float*)d_in[4];
    const float* Wo = (const float*)d_in[5];
    const float* bo = (const float*)d_in[6];
    const float* W1 = (const float*)d_in[7];
    const float* W2 = (const float*)d_in[8];
    const float* b2 = (const float*)d_in[9];
    const float* g1 = (const float*)d_in[10];
    const float* g2 = (const float*)d_in[11];
    const float* gf = (const float*)d_in[12];
    float* out = (float*)d_out;

    float* px;
    __half *pq, *pk, *pv, *ph, *pctx, *pmid;
    __half *wq, *wk, *wv, *wo, *w1, *w2;
    cudaGetSymbolAddress((void**)&px,   g_x);
    cudaGetSymbolAddress((void**)&pq,   g_q);
    cudaGetSymbolAddress((void**)&pk,   g_k);
    cudaGetSymbolAddress((void**)&pv,   g_v);
    cudaGetSymbolAddress((void**)&ph,   g_h);
    cudaGetSymbolAddress((void**)&pctx, g_ctx);
    cudaGetSymbolAddress((void**)&pmid, g_mid);
    cudaGetSymbolAddress((void**)&wq, g_wqh);
    cudaGetSymbolAddress((void**)&wk, g_wkh);
    cudaGetSymbolAddress((void**)&wv, g_wvh);
    cudaGetSymbolAddress((void**)&wo, g_woh);
    cudaGetSymbolAddress((void**)&w1, g_w1h);
    cudaGetSymbolAddress((void**)&w2, g_w2h);

    cudaFuncSetAttribute(gemm_mma_kernel<0>, cudaFuncAttributeMaxDynamicSharedMemorySize, GSM_TOTAL);
    cudaFuncSetAttribute(gemm_mma_kernel<1>, cudaFuncAttributeMaxDynamicSharedMemorySize, GSM_TOTAL);
    cudaFuncSetAttribute(gemm_mma_kernel<2>, cudaFuncAttributeMaxDynamicSharedMemorySize, GSM_TOTAL);
    cudaFuncSetAttribute(attn_mma_kernel, cudaFuncAttributeMaxDynamicSharedMemorySize, AS_TOTAL);

    // ---- single batched weight convert launch (no transpose) ----
    {
        CDesc d;
        const int bHH = (HID * HID) / 4096;   // 1024 blocks
        const int bHI = (HID * ISZ) / 4096;   // 4096 blocks
        int idx = 0, off = 0;
        for (int l = 0; l < NLAYER; l++) {
            long oHH = (long)l * HID * HID, oHI = (long)l * HID * ISZ;
            const float* srcs[6] = {Wq + oHH, Wk + oHH, Wv + oHH, Wo + oHH, W1 + oHI, W2 + oHI};
            __half* dsts[6]      = {wq + oHH, wk + oHH, wv + oHH, wo + oHH, w1 + oHI, w2 + oHI};
            int Bs[6] = {bHH, bHH, bHH, bHH, bHI, bHI};
            for (int j = 0; j < 6; j++) {
                d.src[idx] = srcs[j]; d.dst[idx] = dsts[j];
                d.off[idx] = off; off += Bs[j];
                idx++;
            }
        }
        d.off[NW] = off;
        wconv_all_kernel<<<off, 256>>>(d);
    }

    dim3 gAttn(SEQ / 128, NHEAD);
    const int ntHH = (HID / 128) * (SEQ / 128);
    const int ntQKV = ntHH * 3;
    const int ntHI = (ISZ / 128) * (SEQ / 128);
    int gQKV = ntQKV < PERSIST_GRID ? ntQKV : PERSIST_GRID;
    int gHH  = ntHH  < PERSIST_GRID ? ntHH  : PERSIST_GRID;
    int gHI  = ntHI  < PERSIST_GRID ? ntHI  : PERSIST_GRID;

    for (int l = 0; l < NLAYER; l++) {
        long oHH = (long)l * HID * HID, oHI = (long)l * HID * ISZ;
        const float* xin = (l == 0) ? emb : px;

        ln_kernel<1><<<SEQ, 256>>>(xin, g1 + l * HID, nullptr, ph);
        gemm_mma_kernel<0><<<gQKV, 128, GSM_TOTAL>>>(ph,
            wq + oHH, wk + oHH, wv + oHH,
            nullptr, nullptr, nullptr, pq, pk, pv,
            SEQ, HID, HID, HID / 128, SEQ / 128, 3);
        attn_mma_kernel<<<gAttn, 256, AS_TOTAL>>>(pq, pk, pv, pctx);
        gemm_mma_kernel<1><<<gHH, 128, GSM_TOTAL>>>(pctx,
            wo + oHH, nullptr, nullptr,
            bo + l * HID, xin, px, nullptr, nullptr, nullptr,
            SEQ, HID, HID, HID / 128, SEQ / 128, 1);

        ln_kernel<1><<<SEQ, 256>>>(px, g2 + l * HID, nullptr, ph);
        gemm_mma_kernel<2><<<gHI, 128, GSM_TOTAL>>>(ph,
            w1 + oHI, nullptr, nullptr,
            nullptr, nullptr, nullptr, pmid, nullptr, nullptr,
            SEQ, ISZ, HID, ISZ / 128, SEQ / 128, 1);
        gemm_mma_kernel<1><<<gHH, 128, GSM_TOTAL>>>(pmid,
            w2 + oHI, nullptr, nullptr,
            b2 + l * HID, px, px, nullptr, nullptr, nullptr,
            SEQ, HID, ISZ, HID / 128, SEQ / 128, 1);
    }

    ln_kernel<0><<<SEQ, 256>>>(px, gf, out, nullptr);
}

// round 16
// speedup vs baseline: 1.1381x; 1.1381x over previous
#include <cuda_runtime.h>
#include <cuda_fp16.h>
#include <math.h>
#include <stdint.h>

#define SEQ 2048
#define HID 2048
#define NHEAD 32
#define HDIM 64
#define ISZ 8192
#define NLAYER 2

// ======================= scratch (static device arrays) =======================
__device__ float g_x  [SEQ * HID];
__device__ __half g_q  [SEQ * HID];
__device__ __half g_k  [SEQ * HID];
__device__ __half g_v  [SEQ * HID];
__device__ __half g_h  [SEQ * HID];
__device__ __half g_ctx[SEQ * HID];
__device__ __half g_mid[SEQ * ISZ];
// transposed weights: Wt[N][K], plain fp16
__device__ __half g_wqt[NLAYER * HID * HID];
__device__ __half g_wkt[NLAYER * HID * HID];
__device__ __half g_wvt[NLAYER * HID * HID];
__device__ __half g_wot[NLAYER * HID * HID];
__device__ __half g_w1t[NLAYER * HID * ISZ];
__device__ __half g_w2t[NLAYER * ISZ * HID];

// ======================= PTX helpers =======================
__device__ __forceinline__ uint32_t smem_u32(const void* p) {
    uint32_t a;
    asm("{ .reg .u64 t; cvta.to.shared.u64 t, %1; cvt.u32.u64 %0, t; }" : "=r"(a) : "l"(p));
    return a;
}
__device__ __forceinline__ void cp16(uint32_t dst, const void* src) {
    asm volatile("cp.async.cg.shared.global [%0], [%1], 16;" :: "r"(dst), "l"(src));
}
__device__ __forceinline__ void cp_commit() {
    asm volatile("cp.async.commit_group;" ::: "memory");
}
template <int N>
__device__ __forceinline__ void cp_wait() {
    asm volatile("cp.async.wait_group %0;" :: "n"(N) : "memory");
}
__device__ __forceinline__ void ldmx4(uint32_t* r, uint32_t addr) {
    asm volatile("ldmatrix.sync.aligned.m8n8.x4.shared.b16 {%0,%1,%2,%3}, [%4];"
                 : "=r"(r[0]), "=r"(r[1]), "=r"(r[2]), "=r"(r[3]) : "r"(addr));
}
__device__ __forceinline__ void ldmx4t(uint32_t* r, uint32_t addr) {
    asm volatile("ldmatrix.sync.aligned.m8n8.x4.trans.shared.b16 {%0,%1,%2,%3}, [%4];"
                 : "=r"(r[0]), "=r"(r[1]), "=r"(r[2]), "=r"(r[3]) : "r"(addr));
}
__device__ __forceinline__ void mma16816h(float* d, const uint32_t* a, const uint32_t* b) {
    asm volatile("mma.sync.aligned.m16n8k16.row.col.f32.f16.f16.f32 "
                 "{%0,%1,%2,%3}, {%4,%5,%6,%7}, {%8,%9}, {%0,%1,%2,%3};"
                 : "+f"(d[0]), "+f"(d[1]), "+f"(d[2]), "+f"(d[3])
                 : "r"(a[0]), "r"(a[1]), "r"(a[2]), "r"(a[3]), "r"(b[0]), "r"(b[1]));
}
__device__ __forceinline__ uint32_t packh2(float lo, float hi) {
    __half2 t = __floats2half2_rn(lo, hi);
    return *(uint32_t*)&t;
}

// ======================= small kernels =======================
__device__ __forceinline__ float gelu_tanh(float v) {
    float t = 0.7978845608028654f * v * (1.0f + 0.044715f * v * v);
    return 0.5f * v * (1.0f + tanhf(t));
}

// layernorm: single global read (values in registers), vectorized I/O
template <int HALF>
__global__ void __launch_bounds__(256) ln_kernel(const float* __restrict__ x,
                                                 const float* __restrict__ gamma,
                                                 float* __restrict__ outf,
                                                 __half* __restrict__ oh) {
    __shared__ float sh[18];
    int row = blockIdx.x;
    const float4* xr4 = (const float4*)(x + (long)row * HID);
    const float4* g4  = (const float4*)gamma;
    float4 v[2];
    float s = 0.f, s2 = 0.f;
    #pragma unroll
    for (int i = 0; i < 2; i++) {
        v[i] = xr4[threadIdx.x + i * 256];
        s  += v[i].x + v[i].y + v[i].z + v[i].w;
        s2 += v[i].x * v[i].x + v[i].y * v[i].y + v[i].z * v[i].z + v[i].w * v[i].w;
    }
    #pragma unroll
    for (int o = 16; o; o >>= 1) {
        s  += __shfl_xor_sync(0xFFFFFFFFu, s,  o);
        s2 += __shfl_xor_sync(0xFFFFFFFFu, s2, o);
    }
    int w = threadIdx.x >> 5, lane = threadIdx.x & 31;
    if (lane == 0) { sh[w] = s; sh[8 + w] = s2; }
    __syncthreads();
    if (threadIdx.x < 32) {
        s  = (threadIdx.x < 8) ? sh[threadIdx.x]     : 0.f;
        s2 = (threadIdx.x < 8) ? sh[8 + threadIdx.x] : 0.f;
        #pragma unroll
        for (int o = 4; o; o >>= 1) {
            s  += __shfl_xor_sync(0xFFFFFFFFu, s,  o);
            s2 += __shfl_xor_sync(0xFFFFFFFFu, s2, o);
        }
        if (threadIdx.x == 0) {
            float mu = s * (1.0f / HID);
            float var = s2 * (1.0f / HID) - mu * mu;
            sh[16] = mu;
            sh[17] = rsqrtf(var + 1e-5f);
        }
    }
    __syncthreads();
    float mu = sh[16], inv = sh[17];
    #pragma unroll
    for (int i = 0; i < 2; i++) {
        int i4 = threadIdx.x + i * 256;
        float4 g = g4[i4];
        float a = (v[i].x - mu) * inv * g.x;
        float b = (v[i].y - mu) * inv * g.y;
        float c = (v[i].z - mu) * inv * g.z;
        float d = (v[i].w - mu) * inv * g.w;
        if (HALF) {
            uint2 p;
            p.x = packh2(a, b);
            p.y = packh2(c, d);
            *(uint2*)(oh + (long)row * HID + i4 * 4) = p;
        } else {
            *(float4*)(outf + (long)row * HID + i4 * 4) = make_float4(a, b, c, d);
        }
    }
}

// ======================= batched weight transpose (single launch) =======================
// For each of NW weight matrices: W[K,N] fp32 -> Th[N,K] fp16.
// Tile 64(K) x 32(N), 256 threads; coalesced float loads, coalesced __half2 stores.
#define NW 12
struct WDesc {
    const float* src[NW];
    __half* dst[NW];
    int K[NW];
    int N[NW];
    int off[NW + 1];   // tile prefix offsets
};

__global__ void __launch_bounds__(256) wsplit_all_kernel(WDesc d) {
    int bid = blockIdx.x;
    int m = 0;
    #pragma unroll
    for (int i = 0; i < NW; i++)
        if (bid >= d.off[i + 1]) m = i + 1;
    int local = bid - d.off[m];
    int K = d.K[m], N = d.N[m];
    int tiles_x = N >> 5;
    int by = (local / tiles_x) << 6;   // K offset
    int bx = (local % tiles_x) << 5;   // N offset
    const float* W = d.src[m];
    __half* Th = d.dst[m];

    __shared__ float t[64][33];
    int tid = threadIdx.x;
    int c = tid & 31, r0 = tid >> 5;
    #pragma unroll
    for (int i = 0; i < 8; i++)
        t[r0 + i * 8][c] = W[(long)(by + r0 + i * 8) * N + bx + c];
    __syncthreads();
    int kp = tid & 31, n0 = tid >> 5;
    #pragma unroll
    for (int i = 0; i < 4; i++) {
        int n = n0 + i * 8;
        __half2 v = __floats2half2_rn(t[kp * 2][n], t[kp * 2 + 1][n]);
        *(__half2*)(Th + (long)(bx + n) * K + by + kp * 2) = v;
    }
}

// ======================= persistent mma.sync fp16 GEMM (64x64 warp tiles) =======================
#define T_TILE 8192
#define STAGE_BYTES (2 * T_TILE)
#define NSTAGE 4
#define GSM_TOTAL (NSTAGE * STAGE_BYTES)
#define PERSIST_GRID 296

__device__ __forceinline__ void load_tile64(uint32_t sbase, const __half* __restrict__ P,
                                            int K, long k0, int tid) {
    #pragma unroll
    for (int i = 0; i < 4; i++) {
        int idx = tid + i * 128;
        int row = idx >> 2, c = idx & 3;
        const __half* src = P + (long)row * K + k0 + c * 8;
        uint32_t dst = sbase + row * 64 + ((c ^ ((row >> 1) & 3)) << 4);
        cp16(dst, src);
    }
}

template <int MODE>
__global__ void __launch_bounds__(128, 2) gemm_mma_kernel(
    const __half* __restrict__ A,
    const __half* __restrict__ B0, const __half* __restrict__ B1,
    const __half* __restrict__ B2,
    const float* __restrict__ bias, const float* res,
    float* Cf,
    __half* __restrict__ Ch0, __half* __restrict__ Ch1, __half* __restrict__ Ch2,
    int M, int N, int K, int ntx, int nty, int ntz)
{
    extern __shared__ char smem[];
    uint32_t sb = smem_u32(smem);
    int tid = threadIdx.x;
    int wid = tid >> 5, lane = tid & 31;
    int warp_m = wid >> 1, warp_n = wid & 1;
    int m0 = warp_m * 64, n0 = warp_n * 64;

    int grp = lane >> 3, lr = lane & 7;
    int rowA0 = m0 + (grp & 1) * 8 + lr;
    int ccA   = grp >> 1;
    int rowB0 = n0 + (grp >> 1) * 8 + lr;
    int ccB   = grp & 1;
    int xA = (rowA0 >> 1) & 3;
    int xB = (rowB0 >> 1) & 3;
    int nc = K / 32;
    int ntot = ntx * nty * ntz;

    for (int t = blockIdx.x; t < ntot; t += gridDim.x) {
        int z   = t / (ntx * nty);
        int rem = t - z * (ntx * nty);
        int by  = rem / ntx;
        int bx  = rem - by * ntx;
        int row0 = by * 128, col0 = bx * 128;

        const __half* B  = (z == 0) ? B0 : (z == 1) ? B1 : B2;
        __half* Ch = (z == 0) ? Ch0 : (z == 1) ? Ch1 : Ch2;

        const __half* pA = A + (long)row0 * K;
        const __half* pB = B + (long)col0 * K;

        float acc[4][8][4];
        #pragma unroll
        for (int i = 0; i < 4; i++)
            #pragma unroll
            for (int j = 0; j < 8; j++)
                #pragma unroll
                for (int q = 0; q < 4; q++) acc[i][j][q] = 0.f;

        __syncthreads();

        #pragma unroll
        for (int p = 0; p < 3; p++) {
            uint32_t st = sb + p * STAGE_BYTES;
            load_tile64(st,          pA, K, (long)p * 32, tid);
            load_tile64(st + T_TILE, pB, K, (long)p * 32, tid);
            cp_commit();
        }

        int s_comp = 0, s_load = 3;
        for (int c = 0; c < nc; c++) {
            cp_wait<2>();
            __syncthreads();
            if (c + 3 < nc) {
                uint32_t st = sb + s_load * STAGE_BYTES;
                long k0 = (long)(c + 3) * 32;
                load_tile64(st,          pA, K, k0, tid);
                load_tile64(st + T_TILE, pB, K, k0, tid);
            }
            cp_commit();

            uint32_t sA = sb + s_comp * STAGE_BYTES;
            uint32_t sB = sA + T_TILE;
            #pragma unroll
            for (int ks = 0; ks < 2; ks++) {
                uint32_t af[4][4], bf[4][4];
                #pragma unroll
                for (int mt = 0; mt < 4; mt++) {
                    uint32_t base = sA + (rowA0 + mt * 16) * 64;
                    ldmx4(af[mt], base + (((ks * 2 + ccA) ^ xA) << 4));
                }
                #pragma unroll
                for (int np = 0; np < 4; np++) {
                    uint32_t base = sB + (rowB0 + np * 16) * 64;
                    ldmx4(bf[np], base + (((ks * 2 + ccB) ^ xB) << 4));
                }
                #pragma unroll
                for (int mt = 0; mt < 4; mt++)
                    #pragma unroll
                    for (int nt = 0; nt < 8; nt++)
                        mma16816h(acc[mt][nt], af[mt], &bf[nt >> 1][(nt & 1) * 2]);
            }
            s_comp = (s_comp + 1) & 3;
            s_load = (s_load + 1) & 3;
        }

        int r = lane >> 2, c2 = (lane & 3) * 2;
        #pragma unroll
        for (int mt = 0; mt < 4; mt++) {
            #pragma unroll
            for (int nt = 0; nt < 8; nt++) {
                long gr = row0 + m0 + mt * 16 + r;
                long gc = col0 + n0 + nt * 8 + c2;
                #pragma unroll
                for (int hrow = 0; hrow < 2; hrow++) {
                    long grr = gr + hrow * 8;
                    float v0 = acc[mt][nt][hrow * 2 + 0];
                    float v1 = acc[mt][nt][hrow * 2 + 1];
                    if (MODE == 0) {
                        *(uint32_t*)(Ch + grr * N + gc) = packh2(v0, v1);
                    } else if (MODE == 1) {
                        float2 b = *(const float2*)(bias + gc);
                        float2 rr = *(const float2*)(res + grr * N + gc);
                        *(float2*)(Cf + grr * N + gc) = make_float2(v0 + b.x + rr.x, v1 + b.y + rr.y);
                    } else {
                        *(uint32_t*)(Ch + grr * N + gc) = packh2(gelu_tanh(v0), gelu_tanh(v1));
                    }
                }
            }
        }
    }
}

// ======================= tensor-core flash attention (plain fp16) =======================
#define AS_Q  0
#define AS_K0 16384
#define AS_V0 32768
#define AS_K1 49152
#define AS_V1 65536
#define AS_TOTAL 81920

__device__ __forceinline__ void stage_h(uint32_t sbase, const __half* __restrict__ src,
                                        int row0, int h, int tid) {
    #pragma unroll
    for (int i = 0; i < 4; i++) {
        int idx = tid + i * 256;
        int r = idx >> 3, c = idx & 7;
        cp16(sbase + r * 128 + ((c ^ (r & 7)) << 4),
             src + (long)(row0 + r) * HID + h * HDIM + c * 8);
    }
}

__global__ void __launch_bounds__(256) attn_mma_kernel(
    const __half* __restrict__ Q, const __half* __restrict__ K,
    const __half* __restrict__ V, __half* __restrict__ O)
{
    extern __shared__ char smem[];
    uint32_t sb = smem_u32(smem);
    int tid = threadIdx.x;
    int w = tid >> 5, lane = tid & 31;
    // heavy blocks (large qb) first: reverse mapping shortens the last wave's tail
    int qb = gridDim.x - 1 - blockIdx.x;
    int h = blockIdx.y;

    int grp = lane >> 3, lr = lane & 7;
    int rowQ = w * 16 + (grp & 1) * 8 + lr;
    int ccQ  = grp >> 1;
    int xQ = rowQ & 7;
    int rowK_off = (grp >> 1) * 8 + lr;
    int ccK  = grp & 1;
    int rowV_off = (grp & 1) * 8 + lr;
    int ccV_off  = grp >> 1;

    stage_h(sb + AS_Q,  Q, qb * 128, h, tid);
    stage_h(sb + AS_K0, K, 0,        h, tid);
    stage_h(sb + AS_V0, V, 0,        h, tid);
    cp_commit();
    cp_wait<0>();
    __syncthreads();

    uint32_t qf[4][4];
    #pragma unroll
    for (int ks = 0; ks < 4; ks++) {
        uint32_t base = sb + AS_Q + rowQ * 128;
        ldmx4(qf[ks], base + (((ks * 2 + ccQ) ^ xQ) << 4));
    }

    float oacc[8][4];
    #pragma unroll
    for (int i = 0; i < 8; i++)
        #pragma unroll
        for (int q = 0; q < 4; q++) oacc[i][q] = 0.f;
    float m0 = -1e30f, m1 = -1e30f, l0 = 0.f, l1 = 0.f;

    int qg0 = qb * 128 + w * 16 + (lane >> 2);
    int qg1 = qg0 + 8;
    const float scale = 0.125f;

    for (int kt = 0; kt <= qb; kt++) {
        uint32_t kb = sb + ((kt & 1) ? AS_K1 : AS_K0);
        uint32_t vb = sb + ((kt & 1) ? AS_V1 : AS_V0);
        if (kt < qb) {
            uint32_t kb2 = sb + ((kt & 1) ? AS_K0 : AS_K1);
            uint32_t vb2 = sb + ((kt & 1) ? AS_V0 : AS_V1);
            stage_h(kb2, K, (kt + 1) * 128, h, tid);
            stage_h(vb2, V, (kt + 1) * 128, h, tid);
            cp_commit();
        }

        float sacc[16][4];
        #pragma unroll
        for (int i = 0; i < 16; i++)
            #pragma unroll
            for (int q = 0; q < 4; q++) sacc[i][q] = 0.f;

        #pragma unroll
        for (int ks = 0; ks < 4; ks++) {
            #pragma unroll
            for (int nb = 0; nb < 8; nb++) {
                int rowK = nb * 16 + rowK_off;
                uint32_t bk[4];
                ldmx4(bk, kb + rowK * 128 + (((ks * 2 + ccK) ^ (rowK & 7)) << 4));
                mma16816h(sacc[nb * 2 + 0], qf[ks], &bk[0]);
                mma16816h(sacc[nb * 2 + 1], qf[ks], &bk[2]);
            }
        }
        #pragma unroll
        for (int nt = 0; nt < 16; nt++) {
            sacc[nt][0] *= scale; sacc[nt][1] *= scale;
            sacc[nt][2] *= scale; sacc[nt][3] *= scale;
        }

        if (kt == qb) {
            #pragma unroll
            for (int nt = 0; nt < 16; nt++) {
                int kg = kt * 128 + nt * 8 + 2 * (lane & 3);
                #pragma unroll
                for (int e = 0; e < 2; e++) {
                    if (kg + e > qg0) sacc[nt][e]     = -1e30f;
                    if (kg + e > qg1) sacc[nt][2 + e] = -1e30f;
                }
            }
        }

        float rm0 = -1e30f, rm1 = -1e30f;
        #pragma unroll
        for (int nt = 0; nt < 16; nt++) {
            rm0 = fmaxf(rm0, fmaxf(sacc[nt][0], sacc[nt][1]));
            rm1 = fmaxf(rm1, fmaxf(sacc[nt][2], sacc[nt][3]));
        }
        rm0 = fmaxf(rm0, __shfl_xor_sync(0xFFFFFFFFu, rm0, 1));
        rm0 = fmaxf(rm0, __shfl_xor_sync(0xFFFFFFFFu, rm0, 2));
        rm1 = fmaxf(rm1, __shfl_xor_sync(0xFFFFFFFFu, rm1, 1));
        rm1 = fmaxf(rm1, __shfl_xor_sync(0xFFFFFFFFu, rm1, 2));
        float mn0 = fmaxf(m0, rm0), mn1 = fmaxf(m1, rm1);
        float al0 = __expf(m0 - mn0), al1 = __expf(m1 - mn1);
        m0 = mn0; m1 = mn1;

        float rs0 = 0.f, rs1 = 0.f;
        #pragma unroll
        for (int nt = 0; nt < 16; nt++) {
            sacc[nt][0] = __expf(sacc[nt][0] - mn0);
            sacc[nt][1] = __expf(sacc[nt][1] - mn0);
            sacc[nt][2] = __expf(sacc[nt][2] - mn1);
            sacc[nt][3] = __expf(sacc[nt][3] - mn1);
            rs0 += sacc[nt][0] + sacc[nt][1];
            rs1 += sacc[nt][2] + sacc[nt][3];
        }
        rs0 += __shfl_xor_sync(0xFFFFFFFFu, rs0, 1);
        rs0 += __shfl_xor_sync(0xFFFFFFFFu, rs0, 2);
        rs1 += __shfl_xor_sync(0xFFFFFFFFu, rs1, 1);
        rs1 += __shfl_xor_sync(0xFFFFFFFFu, rs1, 2);
        l0 = l0 * al0 + rs0;
        l1 = l1 * al1 + rs1;

        #pragma unroll
        for (int i = 0; i < 8; i++) {
            oacc[i][0] *= al0; oacc[i][1] *= al0;
            oacc[i][2] *= al1; oacc[i][3] *= al1;
        }

        #pragma unroll
        for (int ks2 = 0; ks2 < 8; ks2++) {
            uint32_t ap[4];
            ap[0] = packh2(sacc[2 * ks2][0],     sacc[2 * ks2][1]);
            ap[1] = packh2(sacc[2 * ks2][2],     sacc[2 * ks2][3]);
            ap[2] = packh2(sacc[2 * ks2 + 1][0], sacc[2 * ks2 + 1][1]);
            ap[3] = packh2(sacc[2 * ks2 + 1][2], sacc[2 * ks2 + 1][3]);
            int rowV = ks2 * 16 + rowV_off;
            uint32_t vbase = vb + rowV * 128;
            #pragma unroll
            for (int db = 0; db < 4; db++) {
                int cc = db * 2 + ccV_off;
                uint32_t bv[4];
                ldmx4t(bv, vbase + ((cc ^ (rowV & 7)) << 4));
                mma16816h(oacc[db * 2 + 0], ap, &bv[0]);
                mma16816h(oacc[db * 2 + 1], ap, &bv[2]);
            }
        }

        if (kt < qb) {
            cp_wait<0>();
            __syncthreads();
        }
    }

    float i0 = 1.0f / l0, i1 = 1.0f / l1;
    long gr0 = qb * 128 + w * 16 + (lane >> 2);
    long gc0 = h * HDIM + 2 * (lane & 3);
    #pragma unroll
    for (int nto = 0; nto < 8; nto++) {
        long gc = gc0 + nto * 8;
        *(uint32_t*)(O + gr0 * HID + gc)       = packh2(oacc[nto][0] * i0, oacc[nto][1] * i0);
        *(uint32_t*)(O + (gr0 + 8) * HID + gc) = packh2(oacc[nto][2] * i1, oacc[nto][3] * i1);
    }
}

// ======================= orchestration =======================
extern "C" void kernel_launch(void* const* d_in, const int* in_sizes, int n_in,
                              void* d_out, int out_size) {
    const float* emb = (const float*)d_in[0];
    const float* Wq = (const float*)d_in[2];
    const float* Wk = (const float*)d_in[3];
    const float* Wv = (const float*)d_in[4];
    const float* Wo = (const float*)d_in[5];
    const float* bo = (const float*)d_in[6];
    const float* W1 = (const float*)d_in[7];
    const float* W2 = (const float*)d_in[8];
    const float* b2 = (const float*)d_in[9];
    const float* g1 = (const float*)d_in[10];
    const float* g2 = (const float*)d_in[11];
    const float* gf = (const float*)d_in[12];
    float* out = (float*)d_out;

    float* px;
    __half *pq, *pk, *pv, *ph, *pctx, *pmid;
    __half *wq, *wk, *wv, *wo, *w1, *w2;
    cudaGetSymbolAddress((void**)&px,   g_x);
    cudaGetSymbolAddress((void**)&pq,   g_q);
    cudaGetSymbolAddress((void**)&pk,   g_k);
    cudaGetSymbolAddress((void**)&pv,   g_v);
    cudaGetSymbolAddress((void**)&ph,   g_h);
    cudaGetSymbolAddress((void**)&pctx, g_ctx);
    cudaGetSymbolAddress((void**)&pmid, g_mid);
    cudaGetSymbolAddress((void**)&wq, g_wqt);
    cudaGetSymbolAddress((void**)&wk, g_wkt);
    cudaGetSymbolAddress((void**)&wv, g_wvt);
    cudaGetSymbolAddress((void**)&wo, g_wot);
    cudaGetSymbolAddress((void**)&w1, g_w1t);
    cudaGetSymbolAddress((void**)&w2, g_w2t);

    cudaFuncSetAttribute(gemm_mma_kernel<0>, cudaFuncAttributeMaxDynamicSharedMemorySize, GSM_TOTAL);
    cudaFuncSetAttribute(gemm_mma_kernel<1>, cudaFuncAttributeMaxDynamicSharedMemorySize, GSM_TOTAL);
    cudaFuncSetAttribute(gemm_mma_kernel<2>, cudaFuncAttributeMaxDynamicSharedMemorySize, GSM_TOTAL);
    cudaFuncSetAttribute(attn_mma_kernel, cudaFuncAttributeMaxDynamicSharedMemorySize, AS_TOTAL);

    // ---- single batched weight transpose launch ----
    {
        WDesc d;
        const int tHH = (HID / 64) * (HID / 32);
        const int tW1 = (HID / 64) * (ISZ / 32);
        const int tW2 = (ISZ / 64) * (HID / 32);
        int idx = 0, off = 0;
        for (int l = 0; l < NLAYER; l++) {
            long oHH = (long)l * HID * HID, oHI = (long)l * HID * ISZ;
            const float* srcs[6] = {Wq + oHH, Wk + oHH, Wv + oHH, Wo + oHH, W1 + oHI, W2 + oHI};
            __half* dsts[6]      = {wq + oHH, wk + oHH, wv + oHH, wo + oHH, w1 + oHI, w2 + oHI};
            int Ks[6] = {HID, HID, HID, HID, HID, ISZ};
            int Ns[6] = {HID, HID, HID, HID, ISZ, HID};
            int Ts[6] = {tHH, tHH, tHH, tHH, tW1, tW2};
            for (int j = 0; j < 6; j++) {
                d.src[idx] = srcs[j]; d.dst[idx] = dsts[j];
                d.K[idx] = Ks[j]; d.N[idx] = Ns[j];
                d.off[idx] = off; off += Ts[j];
                idx++;
            }
        }
        d.off[NW] = off;
        wsplit_all_kernel<<<off, 256>>>(d);
    }

    dim3 gAttn(SEQ / 128, NHEAD);
    const int ntHH = (HID / 128) * (SEQ / 128);
    const int ntQKV = ntHH * 3;
    const int ntHI = (ISZ / 128) * (SEQ / 128);
    int gQKV = ntQKV < PERSIST_GRID ? ntQKV : PERSIST_GRID;
    int gHH  = ntHH  < PERSIST_GRID ? ntHH  : PERSIST_GRID;
    int gHI  = ntHI  < PERSIST_GRID ? ntHI  : PERSIST_GRID;

    for (int l = 0; l < NLAYER; l++) {
        long oHH = (long)l * HID * HID, oHI = (long)l * HID * ISZ;
        const float* xin = (l == 0) ? emb : px;

        ln_kernel<1><<<SEQ, 256>>>(xin, g1 + l * HID, nullptr, ph);
        gemm_mma_kernel<0><<<gQKV, 128, GSM_TOTAL>>>(ph,
            wq + oHH, wk + oHH, wv + oHH,
            nullptr, nullptr, nullptr, pq, pk, pv,
            SEQ, HID, HID, HID / 128, SEQ / 128, 3);
        attn_mma_kernel<<<gAttn, 256, AS_TOTAL>>>(pq, pk, pv, pctx);
        gemm_mma_kernel<1><<<gHH, 128, GSM_TOTAL>>>(pctx,
            wo + oHH, nullptr, nullptr,
            bo + l * HID, xin, px, nullptr, nullptr, nullptr,
            SEQ, HID, HID, HID / 128, SEQ / 128, 1);

        ln_kernel<1><<<SEQ, 256>>>(px, g2 + l * HID, nullptr, ph);
        gemm_mma_kernel<2><<<gHI, 128, GSM_TOTAL>>>(ph,
            w1 + oHI, nullptr, nullptr,
            nullptr, nullptr, nullptr, pmid, nullptr, nullptr,
            SEQ, ISZ, HID, ISZ / 128, SEQ / 128, 1);
        gemm_mma_kernel<1><<<gHH, 128, GSM_TOTAL>>>(pmid,
            w2 + oHI, nullptr, nullptr,
            b2 + l * HID, px, px, nullptr, nullptr, nullptr,
            SEQ, HID, ISZ, HID / 128, SEQ / 128, 1);
    }

    ln_kernel<0><<<SEQ, 256>>>(px, gf, out, nullptr);
}

// round 17
// speedup vs baseline: 1.1430x; 1.0043x over previous
#include <cuda_runtime.h>
#include <cuda_fp16.h>
#include <math.h>
#include <stdint.h>

#define SEQ 2048
#define HID 2048
#define NHEAD 32
#define HDIM 64
#define ISZ 8192
#define NLAYER 2

// ======================= scratch (static device arrays) =======================
__device__ float g_x  [SEQ * HID];
__device__ __half g_q  [SEQ * HID];
__device__ __half g_k  [SEQ * HID];
__device__ __half g_v  [SEQ * HID];
__device__ __half g_h  [SEQ * HID];
__device__ __half g_ctx[SEQ * HID];
__device__ __half g_mid[SEQ * ISZ];
// transposed weights: Wt[N][K], plain fp16
__device__ __half g_wqt[NLAYER * HID * HID];
__device__ __half g_wkt[NLAYER * HID * HID];
__device__ __half g_wvt[NLAYER * HID * HID];
__device__ __half g_wot[NLAYER * HID * HID];
__device__ __half g_w1t[NLAYER * HID * ISZ];
__device__ __half g_w2t[NLAYER * ISZ * HID];

// ======================= PTX helpers =======================
__device__ __forceinline__ uint32_t smem_u32(const void* p) {
    uint32_t a;
    asm("{ .reg .u64 t; cvta.to.shared.u64 t, %1; cvt.u32.u64 %0, t; }" : "=r"(a) : "l"(p));
    return a;
}
__device__ __forceinline__ void cp16(uint32_t dst, const void* src) {
    asm volatile("cp.async.cg.shared.global [%0], [%1], 16;" :: "r"(dst), "l"(src));
}
__device__ __forceinline__ void cp_commit() {
    asm volatile("cp.async.commit_group;" ::: "memory");
}
template <int N>
__device__ __forceinline__ void cp_wait() {
    asm volatile("cp.async.wait_group %0;" :: "n"(N) : "memory");
}
__device__ __forceinline__ void ldmx4(uint32_t* r, uint32_t addr) {
    asm volatile("ldmatrix.sync.aligned.m8n8.x4.shared.b16 {%0,%1,%2,%3}, [%4];"
                 : "=r"(r[0]), "=r"(r[1]), "=r"(r[2]), "=r"(r[3]) : "r"(addr));
}
__device__ __forceinline__ void ldmx4t(uint32_t* r, uint32_t addr) {
    asm volatile("ldmatrix.sync.aligned.m8n8.x4.trans.shared.b16 {%0,%1,%2,%3}, [%4];"
                 : "=r"(r[0]), "=r"(r[1]), "=r"(r[2]), "=r"(r[3]) : "r"(addr));
}
__device__ __forceinline__ void mma16816h(float* d, const uint32_t* a, const uint32_t* b) {
    asm volatile("mma.sync.aligned.m16n8k16.row.col.f32.f16.f16.f32 "
                 "{%0,%1,%2,%3}, {%4,%5,%6,%7}, {%8,%9}, {%0,%1,%2,%3};"
                 : "+f"(d[0]), "+f"(d[1]), "+f"(d[2]), "+f"(d[3])
                 : "r"(a[0]), "r"(a[1]), "r"(a[2]), "r"(a[3]), "r"(b[0]), "r"(b[1]));
}
__device__ __forceinline__ uint32_t packh2(float lo, float hi) {
    __half2 t = __floats2half2_rn(lo, hi);
    return *(uint32_t*)&t;
}

// ======================= small kernels =======================
__device__ __forceinline__ float gelu_tanh(float v) {
    float t = 0.7978845608028654f * v * (1.0f + 0.044715f * v * v);
    return 0.5f * v * (1.0f + tanhf(t));
}

// layernorm: single global read (values in registers), vectorized I/O
template <int HALF>
__global__ void __launch_bounds__(256) ln_kernel(const float* __restrict__ x,
                                                 const float* __restrict__ gamma,
                                                 float* __restrict__ outf,
                                                 __half* __restrict__ oh) {
    __shared__ float sh[18];
    int row = blockIdx.x;
    const float4* xr4 = (const float4*)(x + (long)row * HID);
    const float4* g4  = (const float4*)gamma;
    float4 v[2];
    float s = 0.f, s2 = 0.f;
    #pragma unroll
    for (int i = 0; i < 2; i++) {
        v[i] = xr4[threadIdx.x + i * 256];
        s  += v[i].x + v[i].y + v[i].z + v[i].w;
        s2 += v[i].x * v[i].x + v[i].y * v[i].y + v[i].z * v[i].z + v[i].w * v[i].w;
    }
    #pragma unroll
    for (int o = 16; o; o >>= 1) {
        s  += __shfl_xor_sync(0xFFFFFFFFu, s,  o);
        s2 += __shfl_xor_sync(0xFFFFFFFFu, s2, o);
    }
    int w = threadIdx.x >> 5, lane = threadIdx.x & 31;
    if (lane == 0) { sh[w] = s; sh[8 + w] = s2; }
    __syncthreads();
    if (threadIdx.x < 32) {
        s  = (threadIdx.x < 8) ? sh[threadIdx.x]     : 0.f;
        s2 = (threadIdx.x < 8) ? sh[8 + threadIdx.x] : 0.f;
        #pragma unroll
        for (int o = 4; o; o >>= 1) {
            s  += __shfl_xor_sync(0xFFFFFFFFu, s,  o);
            s2 += __shfl_xor_sync(0xFFFFFFFFu, s2, o);
        }
        if (threadIdx.x == 0) {
            float mu = s * (1.0f / HID);
            float var = s2 * (1.0f / HID) - mu * mu;
            sh[16] = mu;
            sh[17] = rsqrtf(var + 1e-5f);
        }
    }
    __syncthreads();
    float mu = sh[16], inv = sh[17];
    #pragma unroll
    for (int i = 0; i < 2; i++) {
        int i4 = threadIdx.x + i * 256;
        float4 g = g4[i4];
        float a = (v[i].x - mu) * inv * g.x;
        float b = (v[i].y - mu) * inv * g.y;
        float c = (v[i].z - mu) * inv * g.z;
        float d = (v[i].w - mu) * inv * g.w;
        if (HALF) {
            uint2 p;
            p.x = packh2(a, b);
            p.y = packh2(c, d);
            *(uint2*)(oh + (long)row * HID + i4 * 4) = p;
        } else {
            *(float4*)(outf + (long)row * HID + i4 * 4) = make_float4(a, b, c, d);
        }
    }
}

// ======================= batched weight transpose (single launch) =======================
#define NW 12
struct WDesc {
    const float* src[NW];
    __half* dst[NW];
    int K[NW];
    int N[NW];
    int off[NW + 1];
};

__global__ void __launch_bounds__(256) wsplit_all_kernel(WDesc d) {
    int bid = blockIdx.x;
    int m = 0;
    #pragma unroll
    for (int i = 0; i < NW; i++)
        if (bid >= d.off[i + 1]) m = i + 1;
    int local = bid - d.off[m];
    int K = d.K[m], N = d.N[m];
    int tiles_x = N >> 5;
    int by = (local / tiles_x) << 6;
    int bx = (local % tiles_x) << 5;
    const float* W = d.src[m];
    __half* Th = d.dst[m];

    __shared__ float t[64][33];
    int tid = threadIdx.x;
    int c = tid & 31, r0 = tid >> 5;
    #pragma unroll
    for (int i = 0; i < 8; i++)
        t[r0 + i * 8][c] = W[(long)(by + r0 + i * 8) * N + bx + c];
    __syncthreads();
    int kp = tid & 31, n0 = tid >> 5;
    #pragma unroll
    for (int i = 0; i < 4; i++) {
        int n = n0 + i * 8;
        __half2 v = __floats2half2_rn(t[kp * 2][n], t[kp * 2 + 1][n]);
        *(__half2*)(Th + (long)(bx + n) * K + by + kp * 2) = v;
    }
}

// ======================= persistent mma.sync fp16 GEMM (64x64 warp tiles) =======================
#define T_TILE 8192
#define STAGE_BYTES (2 * T_TILE)
#define NSTAGE 4
#define GSM_TOTAL (NSTAGE * STAGE_BYTES)
#define PERSIST_GRID 296

__device__ __forceinline__ void load_tile64(uint32_t sbase, const __half* __restrict__ P,
                                            int K, long k0, int tid) {
    #pragma unroll
    for (int i = 0; i < 4; i++) {
        int idx = tid + i * 128;
        int row = idx >> 2, c = idx & 3;
        const __half* src = P + (long)row * K + k0 + c * 8;
        uint32_t dst = sbase + row * 64 + ((c ^ ((row >> 1) & 3)) << 4);
        cp16(dst, src);
    }
}

template <int MODE>
__global__ void __launch_bounds__(128, 2) gemm_mma_kernel(
    const __half* __restrict__ A,
    const __half* __restrict__ B0, const __half* __restrict__ B1,
    const __half* __restrict__ B2,
    const float* __restrict__ bias, const float* res,
    float* Cf,
    __half* __restrict__ Ch0, __half* __restrict__ Ch1, __half* __restrict__ Ch2,
    int M, int N, int K, int ntx, int nty, int ntz)
{
    extern __shared__ char smem[];
    uint32_t sb = smem_u32(smem);
    int tid = threadIdx.x;
    int wid = tid >> 5, lane = tid & 31;
    int warp_m = wid >> 1, warp_n = wid & 1;
    int m0 = warp_m * 64, n0 = warp_n * 64;

    int grp = lane >> 3, lr = lane & 7;
    int rowA0 = m0 + (grp & 1) * 8 + lr;
    int ccA   = grp >> 1;
    int rowB0 = n0 + (grp >> 1) * 8 + lr;
    int ccB   = grp & 1;
    int xA = (rowA0 >> 1) & 3;
    int xB = (rowB0 >> 1) & 3;
    int nc = K / 32;
    int ntot = ntx * nty * ntz;

    for (int t = blockIdx.x; t < ntot; t += gridDim.x) {
        int z   = t / (ntx * nty);
        int rem = t - z * (ntx * nty);
        int by  = rem / ntx;
        int bx  = rem - by * ntx;
        int row0 = by * 128, col0 = bx * 128;

        const __half* B  = (z == 0) ? B0 : (z == 1) ? B1 : B2;
        __half* Ch = (z == 0) ? Ch0 : (z == 1) ? Ch1 : Ch2;

        const __half* pA = A + (long)row0 * K;
        const __half* pB = B + (long)col0 * K;

        float acc[4][8][4];
        #pragma unroll
        for (int i = 0; i < 4; i++)
            #pragma unroll
            for (int j = 0; j < 8; j++)
                #pragma unroll
                for (int q = 0; q < 4; q++) acc[i][j][q] = 0.f;

        __syncthreads();

        #pragma unroll
        for (int p = 0; p < 3; p++) {
            uint32_t st = sb + p * STAGE_BYTES;
            load_tile64(st,          pA, K, (long)p * 32, tid);
            load_tile64(st + T_TILE, pB, K, (long)p * 32, tid);
            cp_commit();
        }

        int s_comp = 0, s_load = 3;
        for (int c = 0; c < nc; c++) {
            cp_wait<2>();
            __syncthreads();
            if (c + 3 < nc) {
                uint32_t st = sb + s_load * STAGE_BYTES;
                long k0 = (long)(c + 3) * 32;
                load_tile64(st,          pA, K, k0, tid);
                load_tile64(st + T_TILE, pB, K, k0, tid);
            }
            cp_commit();

            uint32_t sA = sb + s_comp * STAGE_BYTES;
            uint32_t sB = sA + T_TILE;
            #pragma unroll
            for (int ks = 0; ks < 2; ks++) {
                uint32_t af[4][4], bf[4][4];
                #pragma unroll
                for (int mt = 0; mt < 4; mt++) {
                    uint32_t base = sA + (rowA0 + mt * 16) * 64;
                    ldmx4(af[mt], base + (((ks * 2 + ccA) ^ xA) << 4));
                }
                #pragma unroll
                for (int np = 0; np < 4; np++) {
                    uint32_t base = sB + (rowB0 + np * 16) * 64;
                    ldmx4(bf[np], base + (((ks * 2 + ccB) ^ xB) << 4));
                }
                #pragma unroll
                for (int mt = 0; mt < 4; mt++)
                    #pragma unroll
                    for (int nt = 0; nt < 8; nt++)
                        mma16816h(acc[mt][nt], af[mt], &bf[nt >> 1][(nt & 1) * 2]);
            }
            s_comp = (s_comp + 1) & 3;
            s_load = (s_load + 1) & 3;
        }

        int r = lane >> 2, c2 = (lane & 3) * 2;
        #pragma unroll
        for (int mt = 0; mt < 4; mt++) {
            #pragma unroll
            for (int nt = 0; nt < 8; nt++) {
                long gr = row0 + m0 + mt * 16 + r;
                long gc = col0 + n0 + nt * 8 + c2;
                #pragma unroll
                for (int hrow = 0; hrow < 2; hrow++) {
                    long grr = gr + hrow * 8;
                    float v0 = acc[mt][nt][hrow * 2 + 0];
                    float v1 = acc[mt][nt][hrow * 2 + 1];
                    if (MODE == 0) {
                        *(uint32_t*)(Ch + grr * N + gc) = packh2(v0, v1);
                    } else if (MODE == 1) {
                        float2 b = *(const float2*)(bias + gc);
                        float2 rr = *(const float2*)(res + grr * N + gc);
                        *(float2*)(Cf + grr * N + gc) = make_float2(v0 + b.x + rr.x, v1 + b.y + rr.y);
                    } else {
                        *(uint32_t*)(Ch + grr * N + gc) = packh2(gelu_tanh(v0), gelu_tanh(v1));
                    }
                }
            }
        }
    }
}

// ======================= tensor-core flash attention (plain fp16, BQ=64, 128 thr) =======================
// Grid: (SEQ/64, NHEAD), 128 threads = 4 warps; warp owns 16 rows x 128 keys.
// SMEM: Q 8KB @0, K0 @8192, V0 @24576, K1 @40960, V1 @57344. Total 73728.
#define AS_Q  0
#define AS_K0 8192
#define AS_V0 24576
#define AS_K1 40960
#define AS_V1 57344
#define AS_TOTAL 73728

// stage 128 KV rows (16KB) with 128 threads
__device__ __forceinline__ void stage_kv(uint32_t sbase, const __half* __restrict__ src,
                                         int row0, int h, int tid) {
    #pragma unroll
    for (int i = 0; i < 8; i++) {
        int idx = tid + i * 128;
        int r = idx >> 3, c = idx & 7;
        cp16(sbase + r * 128 + ((c ^ (r & 7)) << 4),
             src + (long)(row0 + r) * HID + h * HDIM + c * 8);
    }
}
// stage 64 Q rows (8KB) with 128 threads
__device__ __forceinline__ void stage_q(uint32_t sbase, const __half* __restrict__ src,
                                        int row0, int h, int tid) {
    #pragma unroll
    for (int i = 0; i < 4; i++) {
        int idx = tid + i * 128;
        int r = idx >> 3, c = idx & 7;
        cp16(sbase + r * 128 + ((c ^ (r & 7)) << 4),
             src + (long)(row0 + r) * HID + h * HDIM + c * 8);
    }
}

__global__ void __launch_bounds__(128) attn_mma_kernel(
    const __half* __restrict__ Q, const __half* __restrict__ K,
    const __half* __restrict__ V, __half* __restrict__ O)
{
    extern __shared__ char smem[];
    uint32_t sb = smem_u32(smem);
    int tid = threadIdx.x;
    int w = tid >> 5, lane = tid & 31;
    // heavy blocks first
    int qb = gridDim.x - 1 - blockIdx.x;   // q-block of 64 rows
    int h = blockIdx.y;

    int grp = lane >> 3, lr = lane & 7;
    int rowQ = w * 16 + (grp & 1) * 8 + lr;          // < 64
    int ccQ  = grp >> 1;
    int xQ = rowQ & 7;
    int rowK_off = (grp >> 1) * 8 + lr;
    int ccK  = grp & 1;
    int rowV_off = (grp & 1) * 8 + lr;
    int ccV_off  = grp >> 1;

    stage_q (sb + AS_Q,  Q, qb * 64, h, tid);
    stage_kv(sb + AS_K0, K, 0,       h, tid);
    stage_kv(sb + AS_V0, V, 0,       h, tid);
    cp_commit();
    cp_wait<0>();
    __syncthreads();

    uint32_t qf[4][4];
    #pragma unroll
    for (int ks = 0; ks < 4; ks++) {
        uint32_t base = sb + AS_Q + rowQ * 128;
        ldmx4(qf[ks], base + (((ks * 2 + ccQ) ^ xQ) << 4));
    }

    float oacc[8][4];
    #pragma unroll
    for (int i = 0; i < 8; i++)
        #pragma unroll
        for (int q = 0; q < 4; q++) oacc[i][q] = 0.f;
    float m0 = -1e30f, m1 = -1e30f, l0 = 0.f, l1 = 0.f;

    int qg0 = qb * 64 + w * 16 + (lane >> 2);
    int qg1 = qg0 + 8;
    const float scale = 0.125f;

    int nkt = qb >> 1;    // last KV-tile index (128 keys per tile)
    for (int kt = 0; kt <= nkt; kt++) {
        uint32_t kb = sb + ((kt & 1) ? AS_K1 : AS_K0);
        uint32_t vb = sb + ((kt & 1) ? AS_V1 : AS_V0);
        if (kt < nkt) {
            uint32_t kb2 = sb + ((kt & 1) ? AS_K0 : AS_K1);
            uint32_t vb2 = sb + ((kt & 1) ? AS_V0 : AS_V1);
            stage_kv(kb2, K, (kt + 1) * 128, h, tid);
            stage_kv(vb2, V, (kt + 1) * 128, h, tid);
            cp_commit();
        }

        float sacc[16][4];
        #pragma unroll
        for (int i = 0; i < 16; i++)
            #pragma unroll
            for (int q = 0; q < 4; q++) sacc[i][q] = 0.f;

        #pragma unroll
        for (int ks = 0; ks < 4; ks++) {
            #pragma unroll
            for (int nb = 0; nb < 8; nb++) {
                int rowK = nb * 16 + rowK_off;
                uint32_t bk[4];
                ldmx4(bk, kb + rowK * 128 + (((ks * 2 + ccK) ^ (rowK & 7)) << 4));
                mma16816h(sacc[nb * 2 + 0], qf[ks], &bk[0]);
                mma16816h(sacc[nb * 2 + 1], qf[ks], &bk[2]);
            }
        }
        #pragma unroll
        for (int nt = 0; nt < 16; nt++) {
            sacc[nt][0] *= scale; sacc[nt][1] *= scale;
            sacc[nt][2] *= scale; sacc[nt][3] *= scale;
        }

        if (kt == nkt) {
            #pragma unroll
            for (int nt = 0; nt < 16; nt++) {
                int kg = kt * 128 + nt * 8 + 2 * (lane & 3);
                #pragma unroll
                for (int e = 0; e < 2; e++) {
                    if (kg + e > qg0) sacc[nt][e]     = -1e30f;
                    if (kg + e > qg1) sacc[nt][2 + e] = -1e30f;
                }
            }
        }

        float rm0 = -1e30f, rm1 = -1e30f;
        #pragma unroll
        for (int nt = 0; nt < 16; nt++) {
            rm0 = fmaxf(rm0, fmaxf(sacc[nt][0], sacc[nt][1]));
            rm1 = fmaxf(rm1, fmaxf(sacc[nt][2], sacc[nt][3]));
        }
        rm0 = fmaxf(rm0, __shfl_xor_sync(0xFFFFFFFFu, rm0, 1));
        rm0 = fmaxf(rm0, __shfl_xor_sync(0xFFFFFFFFu, rm0, 2));
        rm1 = fmaxf(rm1, __shfl_xor_sync(0xFFFFFFFFu, rm1, 1));
        rm1 = fmaxf(rm1, __shfl_xor_sync(0xFFFFFFFFu, rm1, 2));
        float mn0 = fmaxf(m0, rm0), mn1 = fmaxf(m1, rm1);
        float al0 = __expf(m0 - mn0), al1 = __expf(m1 - mn1);
        m0 = mn0; m1 = mn1;

        float rs0 = 0.f, rs1 = 0.f;
        #pragma unroll
        for (int nt = 0; nt < 16; nt++) {
            sacc[nt][0] = __expf(sacc[nt][0] - mn0);
            sacc[nt][1] = __expf(sacc[nt][1] - mn0);
            sacc[nt][2] = __expf(sacc[nt][2] - mn1);
            sacc[nt][3] = __expf(sacc[nt][3] - mn1);
            rs0 += sacc[nt][0] + sacc[nt][1];
            rs1 += sacc[nt][2] + sacc[nt][3];
        }
        rs0 += __shfl_xor_sync(0xFFFFFFFFu, rs0, 1);
        rs0 += __shfl_xor_sync(0xFFFFFFFFu, rs0, 2);
        rs1 += __shfl_xor_sync(0xFFFFFFFFu, rs1, 1);
        rs1 += __shfl_xor_sync(0xFFFFFFFFu, rs1, 2);
        l0 = l0 * al0 + rs0;
        l1 = l1 * al1 + rs1;

        #pragma unroll
        for (int i = 0; i < 8; i++) {
            oacc[i][0] *= al0; oacc[i][1] *= al0;
            oacc[i][2] *= al1; oacc[i][3] *= al1;
        }

        #pragma unroll
        for (int ks2 = 0; ks2 < 8; ks2++) {
            uint32_t ap[4];
            ap[0] = packh2(sacc[2 * ks2][0],     sacc[2 * ks2][1]);
            ap[1] = packh2(sacc[2 * ks2][2],     sacc[2 * ks2][3]);
            ap[2] = packh2(sacc[2 * ks2 + 1][0], sacc[2 * ks2 + 1][1]);
            ap[3] = packh2(sacc[2 * ks2 + 1][2], sacc[2 * ks2 + 1][3]);
            int rowV = ks2 * 16 + rowV_off;
            uint32_t vbase = vb + rowV * 128;
            #pragma unroll
            for (int db = 0; db < 4; db++) {
                int cc = db * 2 + ccV_off;
                uint32_t bv[4];
                ldmx4t(bv, vbase + ((cc ^ (rowV & 7)) << 4));
                mma16816h(oacc[db * 2 + 0], ap, &bv[0]);
                mma16816h(oacc[db * 2 + 1], ap, &bv[2]);
            }
        }

        if (kt < nkt) {
            cp_wait<0>();
            __syncthreads();
        }
    }

    float i0 = 1.0f / l0, i1 = 1.0f / l1;
    long gr0 = qb * 64 + w * 16 + (lane >> 2);
    long gc0 = h * HDIM + 2 * (lane & 3);
    #pragma unroll
    for (int nto = 0; nto < 8; nto++) {
        long gc = gc0 + nto * 8;
        *(uint32_t*)(O + gr0 * HID + gc)       = packh2(oacc[nto][0] * i0, oacc[nto][1] * i0);
        *(uint32_t*)(O + (gr0 + 8) * HID + gc) = packh2(oacc[nto][2] * i1, oacc[nto][3] * i1);
    }
}

// ======================= orchestration =======================
extern "C" void kernel_launch(void* const* d_in, const int* in_sizes, int n_in,
                              void* d_out, int out_size) {
    const float* emb = (const float*)d_in[0];
    const float* Wq = (const float*)d_in[2];
    const float* Wk = (const float*)d_in[3];
    const float* Wv = (const float*)d_in[4];
    const float* Wo = (const float*)d_in[5];
    const float* bo = (const float*)d_in[6];
    const float* W1 = (const float*)d_in[7];
    const float* W2 = (const float*)d_in[8];
    const float* b2 = (const float*)d_in[9];
    const float* g1 = (const float*)d_in[10];
    const float* g2 = (const float*)d_in[11];
    const float* gf = (const float*)d_in[12];
    float* out = (float*)d_out;

    float* px;
    __half *pq, *pk, *pv, *ph, *pctx, *pmid;
    __half *wq, *wk, *wv, *wo, *w1, *w2;
    cudaGetSymbolAddress((void**)&px,   g_x);
    cudaGetSymbolAddress((void**)&pq,   g_q);
    cudaGetSymbolAddress((void**)&pk,   g_k);
    cudaGetSymbolAddress((void**)&pv,   g_v);
    cudaGetSymbolAddress((void**)&ph,   g_h);
    cudaGetSymbolAddress((void**)&pctx, g_ctx);
    cudaGetSymbolAddress((void**)&pmid, g_mid);
    cudaGetSymbolAddress((void**)&wq, g_wqt);
    cudaGetSymbolAddress((void**)&wk, g_wkt);
    cudaGetSymbolAddress((void**)&wv, g_wvt);
    cudaGetSymbolAddress((void**)&wo, g_wot);
    cudaGetSymbolAddress((void**)&w1, g_w1t);
    cudaGetSymbolAddress((void**)&w2, g_w2t);

    cudaFuncSetAttribute(gemm_mma_kernel<0>, cudaFuncAttributeMaxDynamicSharedMemorySize, GSM_TOTAL);
    cudaFuncSetAttribute(gemm_mma_kernel<1>, cudaFuncAttributeMaxDynamicSharedMemorySize, GSM_TOTAL);
    cudaFuncSetAttribute(gemm_mma_kernel<2>, cudaFuncAttributeMaxDynamicSharedMemorySize, GSM_TOTAL);
    cudaFuncSetAttribute(attn_mma_kernel, cudaFuncAttributeMaxDynamicSharedMemorySize, AS_TOTAL);

    // ---- single batched weight transpose launch ----
    {
        WDesc d;
        const int tHH = (HID / 64) * (HID / 32);
        const int tW1 = (HID / 64) * (ISZ / 32);
        const int tW2 = (ISZ / 64) * (HID / 32);
        int idx = 0, off = 0;
        for (int l = 0; l < NLAYER; l++) {
            long oHH = (long)l * HID * HID, oHI = (long)l * HID * ISZ;
            const float* srcs[6] = {Wq + oHH, Wk + oHH, Wv + oHH, Wo + oHH, W1 + oHI, W2 + oHI};
            __half* dsts[6]      = {wq + oHH, wk + oHH, wv + oHH, wo + oHH, w1 + oHI, w2 + oHI};
            int Ks[6] = {HID, HID, HID, HID, HID, ISZ};
            int Ns[6] = {HID, HID, HID, HID, ISZ, HID};
            int Ts[6] = {tHH, tHH, tHH, tHH, tW1, tW2};
            for (int j = 0; j < 6; j++) {
                d.src[idx] = srcs[j]; d.dst[idx] = dsts[j];
                d.K[idx] = Ks[j]; d.N[idx] = Ns[j];
                d.off[idx] = off; off += Ts[j];
                idx++;
            }
        }
        d.off[NW] = off;
        wsplit_all_kernel<<<off, 256>>>(d);
    }

    dim3 gAttn(SEQ / 64, NHEAD);
    const int ntHH = (HID / 128) * (SEQ / 128);
    const int ntQKV = ntHH * 3;
    const int ntHI = (ISZ / 128) * (SEQ / 128);
    int gQKV = ntQKV < PERSIST_GRID ? ntQKV : PERSIST_GRID;
    int gHH  = ntHH  < PERSIST_GRID ? ntHH  : PERSIST_GRID;
    int gHI  = ntHI  < PERSIST_GRID ? ntHI  : PERSIST_GRID;

    for (int l = 0; l < NLAYER; l++) {
        long oHH = (long)l * HID * HID, oHI = (long)l * HID * ISZ;
        const float* xin = (l == 0) ? emb : px;

        ln_kernel<1><<<SEQ, 256>>>(xin, g1 + l * HID, nullptr, ph);
        gemm_mma_kernel<0><<<gQKV, 128, GSM_TOTAL>>>(ph,
            wq + oHH, wk + oHH, wv + oHH,
            nullptr, nullptr, nullptr, pq, pk, pv,
            SEQ, HID, HID, HID / 128, SEQ / 128, 3);
        attn_mma_kernel<<<gAttn, 128, AS_TOTAL>>>(pq, pk, pv, pctx);
        gemm_mma_kernel<1><<<gHH, 128, GSM_TOTAL>>>(pctx,
            wo + oHH, nullptr, nullptr,
            bo + l * HID, xin, px, nullptr, nullptr, nullptr,
            SEQ, HID, HID, HID / 128, SEQ / 128, 1);

        ln_kernel<1><<<SEQ, 256>>>(px, g2 + l * HID, nullptr, ph);
        gemm_mma_kernel<2><<<gHI, 128, GSM_TOTAL>>>(ph,
            w1 + oHI, nullptr, nullptr,
            nullptr, nullptr, nullptr, pmid, nullptr, nullptr,
            SEQ, ISZ, HID, ISZ / 128, SEQ / 128, 1);
        gemm_mma_kernel<1><<<gHH, 128, GSM_TOTAL>>>(pmid,
            w2 + oHI, nullptr, nullptr,
            b2 + l * HID, px, px, nullptr, nullptr, nullptr,
            SEQ, HID, ISZ, HID / 128, SEQ / 128, 1);
    }

    ln_kernel<0><<<SEQ, 256>>>(px, gf, out, nullptr);
}